// round 14
// baseline (speedup 1.0000x reference)
#include <cuda_runtime.h>
#include <cuda_fp16.h>
#include <math.h>
#include <stdint.h>

#define BATCH   2
#define TSEQ    2048
#define DMODEL  1024
#define NHEADS  16
#define HDIM    64
#define BT      (BATCH*TSEQ)   /* 4096 */
#define SCALE_Q 0.1803368801111137f   /* 0.125 * log2(e) */

// ---------------- scratch (static device arrays; no allocation) ----------------
__device__ float g_rope[TSEQ*HDIM];
__device__ double g_invf[32];
__device__ float g_MpartF[64][HDIM*HDIM];
__device__ float g_M[HDIM*HDIM];
__device__ __half g_xh[(size_t)BT*DMODEL];
__device__ __half g_wh[4*(size_t)DMODEL*DMODEL];   // transposed weights [N][K], fp16
__device__ __half g_qh[BATCH*NHEADS*TSEQ*HDIM];
__device__ __half g_kh[BATCH*NHEADS*TSEQ*HDIM];
__device__ __half g_vh[BATCH*NHEADS*TSEQ*HDIM];
__device__ __half g_ah[(size_t)BT*DMODEL];

// ---------------- PTX helpers (base ISA: cp.async / ldmatrix / mma.sync) --------
__device__ __forceinline__ uint32_t smem_u32(const void* p) {
    uint32_t a;
    asm("{ .reg .u64 t; cvta.to.shared.u64 t, %1; cvt.u32.u64 %0, t; }" : "=r"(a) : "l"(p));
    return a;
}
#define CP16(dst, src) asm volatile("cp.async.cg.shared.global [%0], [%1], 16;" :: "r"(dst), "l"(src))
#define CP_COMMIT()    asm volatile("cp.async.commit_group;" ::: "memory")
#define CP_WAIT1()     asm volatile("cp.async.wait_group 1;" ::: "memory")
#define CP_WAIT0()     asm volatile("cp.async.wait_group 0;" ::: "memory")
#define LDSM4(r, a) \
    asm volatile("ldmatrix.sync.aligned.m8n8.x4.shared.b16 {%0,%1,%2,%3}, [%4];" \
        : "=r"((r)[0]), "=r"((r)[1]), "=r"((r)[2]), "=r"((r)[3]) : "r"(a))
#define LDSM4T(r, a) \
    asm volatile("ldmatrix.sync.aligned.m8n8.x4.trans.shared.b16 {%0,%1,%2,%3}, [%4];" \
        : "=r"((r)[0]), "=r"((r)[1]), "=r"((r)[2]), "=r"((r)[3]) : "r"(a))
__device__ __forceinline__ void mma_f16(float* c, const uint32_t* a, uint32_t b0, uint32_t b1) {
    asm volatile("mma.sync.aligned.m16n8k16.row.col.f32.f16.f16.f32 "
                 "{%0,%1,%2,%3}, {%4,%5,%6,%7}, {%8,%9}, {%0,%1,%2,%3};"
                 : "+f"(c[0]), "+f"(c[1]), "+f"(c[2]), "+f"(c[3])
                 : "r"(a[0]), "r"(a[1]), "r"(a[2]), "r"(a[3]), "r"(b0), "r"(b1));
}
__device__ __forceinline__ float ex2f(float x) {
    float r; asm("ex2.approx.f32 %0, %1;" : "=f"(r) : "f"(x)); return r;
}
__device__ __forceinline__ uint32_t pack_h2(float x, float y) {
    __half2 h = __floats2half2_rn(x, y);
    return *(uint32_t*)&h;
}

// ---------------- rope / gram ----------------
__global__ void invf_kernel() {
    int j = threadIdx.x;
    g_invf[j] = exp(-log(10000.0) * (double)j / 32.0);
}
__global__ void rope_kernel() {
    int s = blockIdx.x, d = threadIdx.x;
    double ang = (double)s * g_invf[d & 31];
    g_rope[s*HDIM + d] = (d < 32) ? (float)cos(ang) : (float)sin(ang);
}
// Gram partials, fp32: 64 blocks x 256 threads; each block one 32-row chunk.
__global__ __launch_bounds__(256) void gram1_kernel() {
    __shared__ float R[32][68];
    const int c = blockIdx.x, tid = threadIdx.x;
    const float* rp = g_rope + (size_t)c*32*HDIM;
    for (int i = tid; i < 32*16; i += 256) {
        int r = i >> 4, q = i & 15;
        *(float4*)&R[r][q*4] = *(const float4*)(rp + r*HDIM + q*4);
    }
    __syncthreads();
    const int d0 = (tid & 15)*4, e0 = (tid >> 4)*4;
    float acc[4][4] = {};
    #pragma unroll 4
    for (int s = 0; s < 32; s++) {
        float4 a = *(const float4*)&R[s][d0];
        float4 b = *(const float4*)&R[s][e0];
        acc[0][0] = fmaf(a.x, b.x, acc[0][0]); acc[0][1] = fmaf(a.x, b.y, acc[0][1]);
        acc[0][2] = fmaf(a.x, b.z, acc[0][2]); acc[0][3] = fmaf(a.x, b.w, acc[0][3]);
        acc[1][0] = fmaf(a.y, b.x, acc[1][0]); acc[1][1] = fmaf(a.y, b.y, acc[1][1]);
        acc[1][2] = fmaf(a.y, b.z, acc[1][2]); acc[1][3] = fmaf(a.y, b.w, acc[1][3]);
        acc[2][0] = fmaf(a.z, b.x, acc[2][0]); acc[2][1] = fmaf(a.z, b.y, acc[2][1]);
        acc[2][2] = fmaf(a.z, b.z, acc[2][2]); acc[2][3] = fmaf(a.z, b.w, acc[2][3]);
        acc[3][0] = fmaf(a.w, b.x, acc[3][0]); acc[3][1] = fmaf(a.w, b.y, acc[3][1]);
        acc[3][2] = fmaf(a.w, b.z, acc[3][2]); acc[3][3] = fmaf(a.w, b.w, acc[3][3]);
    }
    #pragma unroll
    for (int i = 0; i < 4; i++)
        #pragma unroll
        for (int j = 0; j < 4; j++)
            g_MpartF[c][(d0 + i)*HDIM + e0 + j] = acc[i][j];
}
__global__ void gram2_kernel() {
    int d = blockIdx.x, e = threadIdx.x;
    float a = 0.f;
    #pragma unroll
    for (int c = 0; c < 64; c++) a += g_MpartF[c][d*HDIM + e];
    g_M[d*HDIM + e] = a;
}

// ---------------- fused fold+transpose+fp16: wh[2] = (Wv @ blockdiag(M))^T -------
__global__ __launch_bounds__(256) void wvfold_kernel(const float* __restrict__ Wv,
                                                     __half* __restrict__ whv) {
    __shared__ float Wt[32][65];   // [k_local][d]
    __shared__ float Mt[64][33];   // [d][e_local]
    const int n0 = blockIdx.x*32, k0 = blockIdx.y*32;
    const int h0 = n0 >> 6;
    const int e0 = n0 & 63;
    const int tid = threadIdx.x;
    for (int i = tid; i < 32*64; i += 256) {
        int r = i >> 6, c = i & 63;
        Wt[r][c] = Wv[(size_t)(k0 + r)*DMODEL + h0*64 + c];
    }
    for (int i = tid; i < 64*32; i += 256) {
        int d = i >> 5, e = i & 31;
        Mt[d][e] = g_M[d*HDIM + e0 + e];
    }
    __syncthreads();
    const int kl = tid & 31, nl0 = tid >> 5;
    #pragma unroll
    for (int u = 0; u < 4; u++) {
        int nl = nl0 + u*8;
        float acc = 0.f;
        #pragma unroll
        for (int d = 0; d < 64; d++) acc = fmaf(Wt[kl][d], Mt[d][nl], acc);
        whv[(size_t)(n0 + nl)*DMODEL + k0 + kl] = __float2half_rn(acc);
    }
}

// ---------------- fp16 convert of x ----------------
__global__ __launch_bounds__(256) void cvt_kernel(const float* __restrict__ src,
                                                  __half* __restrict__ dst, int n4) {
    int i = blockIdx.x*blockDim.x + threadIdx.x;
    if (i >= n4) return;
    float4 v = ((const float4*)src)[i];
    ((uint2*)dst)[i] = make_uint2(pack_h2(v.x, v.y), pack_h2(v.z, v.w));
}

// ---------------- batched transpose+round: {Wq,Wk,Wo} -> wh slots {0,1,3} --------
__global__ void tsplit3_kernel(const float* __restrict__ Wq,
                               const float* __restrict__ Wk,
                               const float* __restrict__ Wo,
                               __half* __restrict__ wh) {
    const int z = blockIdx.z;
    const float* W = (z == 0) ? Wq : (z == 1) ? Wk : Wo;
    __half* out = wh + (size_t)((z == 2) ? 3 : z)*DMODEL*DMODEL;
    __shared__ float t[32][33];
    int x0 = blockIdx.x*32, y0 = blockIdx.y*32;
    int tx = threadIdx.x, ty = threadIdx.y;
    #pragma unroll
    for (int j = 0; j < 32; j += 8)
        t[ty+j][tx] = W[(size_t)(y0+ty+j)*DMODEL + x0+tx];
    __syncthreads();
    #pragma unroll
    for (int j = 0; j < 32; j += 8)
        out[(size_t)(x0+ty+j)*DMODEL + y0+tx] = __float2half_rn(t[tx][ty+j]);
}

// ---------------- HMMA GEMM: C = Ah @ Bh^T, single fp16, fp32 accum --------------
#define ROWB     80
#define TILEB    (128*ROWB)
#define STAGEB   (2*TILEB)
#define SMEMB    (2*STAGEB)

template<int MODE>
__global__ __launch_bounds__(256) void hgemm_tc(const __half* __restrict__ Ah,
                                                const __half* __restrict__ Bh,
                                                const float* __restrict__ bias,
                                                float* __restrict__ OUT,
                                                __half* __restrict__ QH,
                                                __half* __restrict__ KH,
                                                __half* __restrict__ VH)
{
    extern __shared__ char smem[];
    const uint32_t smem_base = smem_u32(smem);
    const int tid  = threadIdx.x;
    const int lane = tid & 31;
    const int wid  = tid >> 5;
    const int wm   = wid & 3;
    const int wn   = wid >> 2;
    const int br   = blockIdx.y, bc = blockIdx.x;

    const int lrow  = tid >> 2;
    const int chunk = tid & 3;

    const __half* A0 = Ah + (size_t)(br*128 + lrow)*DMODEL + chunk*8;
    const __half* B0 = Bh + (size_t)(bc*128 + lrow)*DMODEL + chunk*8;
    const size_t rstep = (size_t)64*DMODEL;

#define ISSUE(s_, buf_) do { \
    uint32_t sb = smem_base + (buf_)*STAGEB; \
    uint32_t d0 = sb + lrow*ROWB + chunk*16; \
    size_t  go = (size_t)(s_)*32; \
    CP16(d0,         A0 + go); \
    CP16(d0 + TILEB, B0 + go); \
    uint32_t d1 = d0 + 64*ROWB; \
    CP16(d1,         A0 + go + rstep); \
    CP16(d1 + TILEB, B0 + go + rstep); \
} while (0)

    float acc[2][8][4];
    #pragma unroll
    for (int i = 0; i < 2; i++)
        #pragma unroll
        for (int j = 0; j < 8; j++)
            #pragma unroll
            for (int e = 0; e < 4; e++) acc[i][j][e] = 0.f;

    const int m0 = wm*32, n0 = wn*64;
    const int lr = lane & 15, lh = lane >> 4;

    ISSUE(0, 0); CP_COMMIT();

    for (int s = 0; s < 32; s++) {
        if (s + 1 < 32) { ISSUE(s + 1, (s + 1) & 1); CP_COMMIT(); CP_WAIT1(); }
        else            { CP_WAIT0(); }
        __syncthreads();

        const uint32_t As = smem_base + (s & 1)*STAGEB;
        const uint32_t Bs = As + TILEB;
        #pragma unroll
        for (int k = 0; k < 2; k++) {
            const uint32_t koff = k*32 + lh*16;
            uint32_t av[2][4], bq[4][4];
            #pragma unroll
            for (int mi = 0; mi < 2; mi++)
                LDSM4(av[mi], As + (m0 + mi*16 + lr)*ROWB + koff);
            #pragma unroll
            for (int jg = 0; jg < 4; jg++)
                LDSM4(bq[jg], Bs + (n0 + jg*16 + lr)*ROWB + koff);
            #pragma unroll
            for (int mi = 0; mi < 2; mi++)
                #pragma unroll
                for (int j = 0; j < 8; j++)
                    mma_f16(acc[mi][j], av[mi], bq[j>>1][j&1], bq[j>>1][(j&1)+2]);
        }
        __syncthreads();
    }
#undef ISSUE

    // epilogue
    const int g = lane >> 2, t = lane & 3;
    int colbase = bc*128;
    int mm = 0;
    if (MODE == 0) { mm = bc >> 3; colbase = (bc & 7)*128; }
    #pragma unroll
    for (int mi = 0; mi < 2; mi++) {
        #pragma unroll
        for (int rr = 0; rr < 2; rr++) {
            const int row = br*128 + m0 + mi*16 + rr*8 + g;
            #pragma unroll
            for (int j = 0; j < 8; j++) {
                const int col = colbase + n0 + j*8 + t*2;
                float vx = acc[mi][j][rr*2 + 0];
                float vy = acc[mi][j][rr*2 + 1];
                if (MODE == 1) {
                    float2 v; v.x = vx + bias[col]; v.y = vy + bias[col + 1];
                    *(float2*)&OUT[(size_t)row*DMODEL + col] = v;
                } else {
                    int bi = row >> 11, tt = row & 2047;
                    int h = col >> 6, dd = col & 63;
                    size_t o = (((size_t)(bi*NHEADS + h))*TSEQ + tt)*HDIM + dd;
                    __half* P = (mm == 0) ? QH : (mm == 1) ? KH : VH;
                    float sc = (mm == 0) ? SCALE_Q : 1.f;
                    *(uint32_t*)&P[o] = pack_h2(vx*sc, vy*sc);
                }
            }
        }
    }
}

// ---------------- HMMA flash attention -----------------------------------------
// S = Qh K^T (exp2 domain, fp16); O = Phi V; fp32 online softmax.
#define ROWF   144
#define FQH    0
#define FQTOT  (128*ROWF)        /* 18432 */
#define FKH    0
#define FVH    (64*ROWF)
#define FSTG   (2*64*ROWF)       /* 18432 */
#define FSMEM  (FQTOT + 2*FSTG)  /* 55296 */

__global__ __launch_bounds__(256, 2) void flash_hmma(
    const __half* __restrict__ qh,
    const __half* __restrict__ kh,  const __half* __restrict__ vh,
    __half* __restrict__ oh)
{
    extern __shared__ char fsm[];
    const uint32_t sb = smem_u32(fsm);
    const int tid = threadIdx.x, lane = tid & 31, wid = tid >> 5;
    const int bh = blockIdx.y, q0 = blockIdx.x*128;
    const int g = lane >> 2, t = lane & 3, lr = lane & 15, lh = lane >> 4;
    const int wq = wid*16;

    const size_t base = (size_t)bh*TSEQ*HDIM;
    const __half* qp = qh + base + (size_t)q0*HDIM;
    const __half* kp = kh + base;
    const __half* vp = vh + base;

    {
        int r = tid >> 1, c4 = (tid & 1)*4;
        #pragma unroll
        for (int u = 0; u < 4; u++)
            CP16(sb + FQH + r*ROWF + (c4+u)*16, qp + (size_t)r*HDIM + (c4+u)*8);
        CP_COMMIT();
    }

#define FISSUE(kb_, b_) do { \
    int r = tid >> 2, c2 = (tid & 3)*2; \
    uint32_t s0 = sb + FQTOT + (b_)*FSTG; \
    size_t go = (size_t)((kb_)*64 + r)*HDIM; \
    _Pragma("unroll") \
    for (int u = 0; u < 2; u++) { \
        CP16(s0 + FKH + r*ROWF + (c2+u)*16, kp + go + (c2+u)*8); \
        CP16(s0 + FVH + r*ROWF + (c2+u)*16, vp + go + (c2+u)*8); \
    } \
} while (0)

    FISSUE(0, 0); CP_COMMIT();
    CP_WAIT0(); __syncthreads();

    float oacc[8][4];
    #pragma unroll
    for (int j = 0; j < 8; j++)
        #pragma unroll
        for (int e = 0; e < 4; e++) oacc[j][e] = 0.f;
    const float NEGINF = __int_as_float(0xff800000);
    float m0 = NEGINF, m1 = NEGINF, l0 = 0.f, l1 = 0.f;

    for (int kb = 0; kb < 32; kb++) {
        if (kb + 1 < 32) { FISSUE(kb + 1, (kb + 1) & 1); CP_COMMIT(); CP_WAIT1(); }
        else             { CP_WAIT0(); }
        __syncthreads();

        const uint32_t SB = sb + FQTOT + (kb & 1)*FSTG;

        // ---- S = Q K^T (1-term), exp2 domain ----
        float sacc[8][4];
        #pragma unroll
        for (int j = 0; j < 8; j++)
            #pragma unroll
            for (int e = 0; e < 4; e++) sacc[j][e] = 0.f;

        #pragma unroll
        for (int kk = 0; kk < 4; kk++) {
            const uint32_t ko = kk*32 + lh*16;
            uint32_t aq[4];
            LDSM4(aq, sb + FQH + (wq + lr)*ROWF + ko);
            #pragma unroll
            for (int jg = 0; jg < 4; jg++) {
                uint32_t bkh[4];
                LDSM4(bkh, SB + FKH + (jg*16 + lr)*ROWF + ko);
                #pragma unroll
                for (int j2 = 0; j2 < 2; j2++)
                    mma_f16(sacc[jg*2 + j2], aq, bkh[j2], bkh[j2+2]);
            }
        }

        // ---- online softmax (exp2 domain) ----
        float nm0 = NEGINF, nm1 = NEGINF;
        #pragma unroll
        for (int j = 0; j < 8; j++) {
            nm0 = fmaxf(nm0, fmaxf(sacc[j][0], sacc[j][1]));
            nm1 = fmaxf(nm1, fmaxf(sacc[j][2], sacc[j][3]));
        }
        nm0 = fmaxf(nm0, __shfl_xor_sync(0xffffffffu, nm0, 1));
        nm0 = fmaxf(nm0, __shfl_xor_sync(0xffffffffu, nm0, 2));
        nm1 = fmaxf(nm1, __shfl_xor_sync(0xffffffffu, nm1, 1));
        nm1 = fmaxf(nm1, __shfl_xor_sync(0xffffffffu, nm1, 2));
        float M0 = fmaxf(m0, nm0), M1 = fmaxf(m1, nm1);
        bool changed = (M0 != m0) || (M1 != m1);
        float c0 = ex2f(m0 - M0), c1 = ex2f(m1 - M1);
        m0 = M0; m1 = M1;
        float rs0 = 0.f, rs1 = 0.f;
        #pragma unroll
        for (int j = 0; j < 8; j++) {
            sacc[j][0] = ex2f(sacc[j][0] - M0);
            sacc[j][1] = ex2f(sacc[j][1] - M0);
            sacc[j][2] = ex2f(sacc[j][2] - M1);
            sacc[j][3] = ex2f(sacc[j][3] - M1);
            rs0 += sacc[j][0] + sacc[j][1];
            rs1 += sacc[j][2] + sacc[j][3];
        }
        rs0 += __shfl_xor_sync(0xffffffffu, rs0, 1);
        rs0 += __shfl_xor_sync(0xffffffffu, rs0, 2);
        rs1 += __shfl_xor_sync(0xffffffffu, rs1, 1);
        rs1 += __shfl_xor_sync(0xffffffffu, rs1, 2);
        l0 = l0*c0 + rs0;
        l1 = l1*c1 + rs1;
        if (__any_sync(0xffffffffu, changed)) {
            #pragma unroll
            for (int j = 0; j < 8; j++) {
                oacc[j][0] *= c0; oacc[j][1] *= c0;
                oacc[j][2] *= c1; oacc[j][3] *= c1;
            }
        }

        // ---- O += Phi V (1-term); P repacked hi-only from S fragments ----
        const int vrow0 = ((lane >> 3) & 1)*8 + (lane & 7);
        const int vcsub = (lane >> 4)*8;
        #pragma unroll
        for (int kk = 0; kk < 4; kk++) {
            uint32_t ah[4];
            ah[0] = pack_h2(sacc[2*kk][0],   sacc[2*kk][1]);
            ah[1] = pack_h2(sacc[2*kk][2],   sacc[2*kk][3]);
            ah[2] = pack_h2(sacc[2*kk+1][0], sacc[2*kk+1][1]);
            ah[3] = pack_h2(sacc[2*kk+1][2], sacc[2*kk+1][3]);
            const uint32_t vr = (kk*16 + vrow0)*ROWF;
            #pragma unroll
            for (int jj = 0; jj < 4; jj++) {
                uint32_t bvh[4];
                LDSM4T(bvh, SB + FVH + vr + (jj*16 + vcsub)*2);
                #pragma unroll
                for (int j2 = 0; j2 < 2; j2++)
                    mma_f16(oacc[jj*2 + j2], ah, bvh[2*j2], bvh[2*j2+1]);
            }
        }
        __syncthreads();
    }
#undef FISSUE

    const float inv0 = 1.f / l0, inv1 = 1.f / l1;
    const int b = bh >> 4, h = bh & 15;
    const int tok0 = b*TSEQ + q0 + wq + g;
    const int tok1 = tok0 + 8;
    #pragma unroll
    for (int j = 0; j < 8; j++) {
        const int col = h*64 + j*8 + t*2;
        *(uint32_t*)&oh[(size_t)tok0*DMODEL + col] = pack_h2(oacc[j][0]*inv0, oacc[j][1]*inv0);
        *(uint32_t*)&oh[(size_t)tok1*DMODEL + col] = pack_h2(oacc[j][2]*inv1, oacc[j][3]*inv1);
    }
}

// ---------------- launch ----------------
extern "C" void kernel_launch(void* const* d_in, const int* in_sizes, int n_in,
                              void* d_out, int out_size)
{
    const float* x  = (const float*)d_in[0];
    const float* Wq = (const float*)d_in[1];
    const float* Wk = (const float*)d_in[2];
    const float* Wv = (const float*)d_in[3];
    const float* Wo = (const float*)d_in[4];
    const float* bo = (const float*)d_in[5];
    float* out = (float*)d_out;

    __half *xh, *wh, *ah, *qh, *kh, *vh;
    cudaGetSymbolAddress((void**)&xh, g_xh);
    cudaGetSymbolAddress((void**)&wh, g_wh);
    cudaGetSymbolAddress((void**)&ah, g_ah);
    cudaGetSymbolAddress((void**)&qh, g_qh);
    cudaGetSymbolAddress((void**)&kh, g_kh);
    cudaGetSymbolAddress((void**)&vh, g_vh);

    const size_t WSZ = (size_t)DMODEL*DMODEL;

    invf_kernel<<<1, 32>>>();
    rope_kernel<<<TSEQ, HDIM>>>();
    cvt_kernel<<<(BT*DMODEL/4 + 255)/256, 256>>>(x, xh, BT*DMODEL/4);
    gram1_kernel<<<64, 256>>>();
    gram2_kernel<<<HDIM, HDIM>>>();
    tsplit3_kernel<<<dim3(32, 32, 3), dim3(32, 8)>>>(Wq, Wk, Wo, wh);
    wvfold_kernel<<<dim3(32, 32), 256>>>(Wv, wh + 2*WSZ);

    cudaFuncSetAttribute(hgemm_tc<0>, cudaFuncAttributeMaxDynamicSharedMemorySize, SMEMB);
    cudaFuncSetAttribute(hgemm_tc<1>, cudaFuncAttributeMaxDynamicSharedMemorySize, SMEMB);
    cudaFuncSetAttribute(flash_hmma, cudaFuncAttributeMaxDynamicSharedMemorySize, FSMEM);

    // merged QKV projection: grid.x = 24 (3 matrices x 8 col-tiles)
    hgemm_tc<0><<<dim3(24, BT/128), 256, SMEMB>>>(xh, wh, nullptr, nullptr, qh, kh, vh);

    flash_hmma<<<dim3(TSEQ/128, BATCH*NHEADS), 256, FSMEM>>>(qh, kh, vh, ah);

    hgemm_tc<1><<<dim3(8, BT/128), 256, SMEMB>>>(ah, wh + 3*WSZ, bo, out,
                                                 nullptr, nullptr, nullptr);

    (void)in_sizes; (void)n_in; (void)out_size;
}

// round 15
// speedup vs baseline: 1.3690x; 1.3690x over previous
#include <cuda_runtime.h>
#include <cuda_fp16.h>
#include <math.h>
#include <stdint.h>

#define BATCH   2
#define TSEQ    2048
#define DMODEL  1024
#define NHEADS  16
#define HDIM    64
#define BT      (BATCH*TSEQ)   /* 4096 */
#define SCALE_Q 0.1803368801111137f   /* 0.125 * log2(e) */

// ---------------- scratch (static device arrays; no allocation) ----------------
__device__ float g_rope[TSEQ*HDIM];
__device__ double g_invf[32];
__device__ float g_MpartF[64][HDIM*HDIM];
__device__ float g_M[HDIM*HDIM];
__device__ __half g_xh[(size_t)BT*DMODEL];
__device__ __half g_wh[4*(size_t)DMODEL*DMODEL];   // transposed weights [N][K], fp16
__device__ __half g_qh[BATCH*NHEADS*TSEQ*HDIM];
__device__ __half g_kh[BATCH*NHEADS*TSEQ*HDIM];
__device__ __half g_vh[BATCH*NHEADS*TSEQ*HDIM];
__device__ __half g_ah[(size_t)BT*DMODEL];

// ---------------- PTX helpers (base ISA: cp.async / ldmatrix / mma.sync) --------
__device__ __forceinline__ uint32_t smem_u32(const void* p) {
    uint32_t a;
    asm("{ .reg .u64 t; cvta.to.shared.u64 t, %1; cvt.u32.u64 %0, t; }" : "=r"(a) : "l"(p));
    return a;
}
#define CP16(dst, src) asm volatile("cp.async.cg.shared.global [%0], [%1], 16;" :: "r"(dst), "l"(src))
#define CP_COMMIT()    asm volatile("cp.async.commit_group;" ::: "memory")
#define CP_WAIT2()     asm volatile("cp.async.wait_group 2;" ::: "memory")
#define CP_WAIT1()     asm volatile("cp.async.wait_group 1;" ::: "memory")
#define CP_WAIT0()     asm volatile("cp.async.wait_group 0;" ::: "memory")
#define LDSM4(r, a) \
    asm volatile("ldmatrix.sync.aligned.m8n8.x4.shared.b16 {%0,%1,%2,%3}, [%4];" \
        : "=r"((r)[0]), "=r"((r)[1]), "=r"((r)[2]), "=r"((r)[3]) : "r"(a))
#define LDSM4T(r, a) \
    asm volatile("ldmatrix.sync.aligned.m8n8.x4.trans.shared.b16 {%0,%1,%2,%3}, [%4];" \
        : "=r"((r)[0]), "=r"((r)[1]), "=r"((r)[2]), "=r"((r)[3]) : "r"(a))
__device__ __forceinline__ void mma_f16(float* c, const uint32_t* a, uint32_t b0, uint32_t b1) {
    asm volatile("mma.sync.aligned.m16n8k16.row.col.f32.f16.f16.f32 "
                 "{%0,%1,%2,%3}, {%4,%5,%6,%7}, {%8,%9}, {%0,%1,%2,%3};"
                 : "+f"(c[0]), "+f"(c[1]), "+f"(c[2]), "+f"(c[3])
                 : "r"(a[0]), "r"(a[1]), "r"(a[2]), "r"(a[3]), "r"(b0), "r"(b1));
}
__device__ __forceinline__ float ex2f(float x) {
    float r; asm("ex2.approx.f32 %0, %1;" : "=f"(r) : "f"(x)); return r;
}
__device__ __forceinline__ uint32_t pack_h2(float x, float y) {
    __half2 h = __floats2half2_rn(x, y);
    return *(uint32_t*)&h;
}

// ---------------- rope / gram ----------------
__global__ void invf_kernel() {
    int j = threadIdx.x;
    g_invf[j] = exp(-log(10000.0) * (double)j / 32.0);
}
__global__ void rope_kernel() {
    int s = blockIdx.x, d = threadIdx.x;
    double ang = (double)s * g_invf[d & 31];
    g_rope[s*HDIM + d] = (d < 32) ? (float)cos(ang) : (float)sin(ang);
}
// Gram partials, fp32: 64 blocks x 256 threads; each block one 32-row chunk.
__global__ __launch_bounds__(256) void gram1_kernel() {
    __shared__ float R[32][68];
    const int c = blockIdx.x, tid = threadIdx.x;
    const float* rp = g_rope + (size_t)c*32*HDIM;
    for (int i = tid; i < 32*16; i += 256) {
        int r = i >> 4, q = i & 15;
        *(float4*)&R[r][q*4] = *(const float4*)(rp + r*HDIM + q*4);
    }
    __syncthreads();
    const int d0 = (tid & 15)*4, e0 = (tid >> 4)*4;
    float acc[4][4] = {};
    #pragma unroll 4
    for (int s = 0; s < 32; s++) {
        float4 a = *(const float4*)&R[s][d0];
        float4 b = *(const float4*)&R[s][e0];
        acc[0][0] = fmaf(a.x, b.x, acc[0][0]); acc[0][1] = fmaf(a.x, b.y, acc[0][1]);
        acc[0][2] = fmaf(a.x, b.z, acc[0][2]); acc[0][3] = fmaf(a.x, b.w, acc[0][3]);
        acc[1][0] = fmaf(a.y, b.x, acc[1][0]); acc[1][1] = fmaf(a.y, b.y, acc[1][1]);
        acc[1][2] = fmaf(a.y, b.z, acc[1][2]); acc[1][3] = fmaf(a.y, b.w, acc[1][3]);
        acc[2][0] = fmaf(a.z, b.x, acc[2][0]); acc[2][1] = fmaf(a.z, b.y, acc[2][1]);
        acc[2][2] = fmaf(a.z, b.z, acc[2][2]); acc[2][3] = fmaf(a.z, b.w, acc[2][3]);
        acc[3][0] = fmaf(a.w, b.x, acc[3][0]); acc[3][1] = fmaf(a.w, b.y, acc[3][1]);
        acc[3][2] = fmaf(a.w, b.z, acc[3][2]); acc[3][3] = fmaf(a.w, b.w, acc[3][3]);
    }
    #pragma unroll
    for (int i = 0; i < 4; i++)
        #pragma unroll
        for (int j = 0; j < 4; j++)
            g_MpartF[c][(d0 + i)*HDIM + e0 + j] = acc[i][j];
}
__global__ void gram2_kernel() {
    int d = blockIdx.x, e = threadIdx.x;
    float a = 0.f;
    #pragma unroll
    for (int c = 0; c < 64; c++) a += g_MpartF[c][d*HDIM + e];
    g_M[d*HDIM + e] = a;
}

// ---------------- fused fold+transpose+fp16: wh[2] = (Wv @ blockdiag(M))^T -------
__global__ __launch_bounds__(256) void wvfold_kernel(const float* __restrict__ Wv,
                                                     __half* __restrict__ whv) {
    __shared__ float Wt[32][65];   // [k_local][d]
    __shared__ float Mt[64][33];   // [d][e_local]
    const int n0 = blockIdx.x*32, k0 = blockIdx.y*32;
    const int h0 = n0 >> 6;
    const int e0 = n0 & 63;
    const int tid = threadIdx.x;
    for (int i = tid; i < 32*64; i += 256) {
        int r = i >> 6, c = i & 63;
        Wt[r][c] = Wv[(size_t)(k0 + r)*DMODEL + h0*64 + c];
    }
    for (int i = tid; i < 64*32; i += 256) {
        int d = i >> 5, e = i & 31;
        Mt[d][e] = g_M[d*HDIM + e0 + e];
    }
    __syncthreads();
    const int kl = tid & 31, nl0 = tid >> 5;
    #pragma unroll
    for (int u = 0; u < 4; u++) {
        int nl = nl0 + u*8;
        float acc = 0.f;
        #pragma unroll
        for (int d = 0; d < 64; d++) acc = fmaf(Wt[kl][d], Mt[d][nl], acc);
        whv[(size_t)(n0 + nl)*DMODEL + k0 + kl] = __float2half_rn(acc);
    }
}

// ---------------- fp16 convert of x ----------------
__global__ __launch_bounds__(256) void cvt_kernel(const float* __restrict__ src,
                                                  __half* __restrict__ dst, int n4) {
    int i = blockIdx.x*blockDim.x + threadIdx.x;
    if (i >= n4) return;
    float4 v = ((const float4*)src)[i];
    ((uint2*)dst)[i] = make_uint2(pack_h2(v.x, v.y), pack_h2(v.z, v.w));
}

// ---------------- batched transpose+round: {Wq,Wk,Wo} -> wh slots {0,1,3} --------
__global__ void tsplit3_kernel(const float* __restrict__ Wq,
                               const float* __restrict__ Wk,
                               const float* __restrict__ Wo,
                               __half* __restrict__ wh) {
    const int z = blockIdx.z;
    const float* W = (z == 0) ? Wq : (z == 1) ? Wk : Wo;
    __half* out = wh + (size_t)((z == 2) ? 3 : z)*DMODEL*DMODEL;
    __shared__ float t[32][33];
    int x0 = blockIdx.x*32, y0 = blockIdx.y*32;
    int tx = threadIdx.x, ty = threadIdx.y;
    #pragma unroll
    for (int j = 0; j < 32; j += 8)
        t[ty+j][tx] = W[(size_t)(y0+ty+j)*DMODEL + x0+tx];
    __syncthreads();
    #pragma unroll
    for (int j = 0; j < 32; j += 8)
        out[(size_t)(x0+ty+j)*DMODEL + y0+tx] = __float2half_rn(t[tx][ty+j]);
}

// ---------------- HMMA GEMM: C = Ah @ Bh^T, fp16, fp32 accum, 3-stage pipeline ---
#define ROWB     80
#define TILEB    (128*ROWB)
#define STAGEB   (2*TILEB)       /* 20480 */
#define SMEMB    (3*STAGEB)      /* 61440 */

template<int MODE>
__global__ __launch_bounds__(256) void hgemm_tc(const __half* __restrict__ Ah,
                                                const __half* __restrict__ Bh,
                                                const float* __restrict__ bias,
                                                float* __restrict__ OUT,
                                                __half* __restrict__ QH,
                                                __half* __restrict__ KH,
                                                __half* __restrict__ VH)
{
    extern __shared__ char smem[];
    const uint32_t smem_base = smem_u32(smem);
    const int tid  = threadIdx.x;
    const int lane = tid & 31;
    const int wid  = tid >> 5;
    const int wm   = wid & 3;
    const int wn   = wid >> 2;
    const int br   = blockIdx.y, bc = blockIdx.x;

    const int lrow  = tid >> 2;
    const int chunk = tid & 3;

    const __half* A0 = Ah + (size_t)(br*128 + lrow)*DMODEL + chunk*8;
    const __half* B0 = Bh + (size_t)(bc*128 + lrow)*DMODEL + chunk*8;
    const size_t rstep = (size_t)64*DMODEL;

#define ISSUE(s_, buf_) do { \
    uint32_t sb = smem_base + (buf_)*STAGEB; \
    uint32_t d0 = sb + lrow*ROWB + chunk*16; \
    size_t  go = (size_t)(s_)*32; \
    CP16(d0,         A0 + go); \
    CP16(d0 + TILEB, B0 + go); \
    uint32_t d1 = d0 + 64*ROWB; \
    CP16(d1,         A0 + go + rstep); \
    CP16(d1 + TILEB, B0 + go + rstep); \
} while (0)

    float acc[2][8][4];
    #pragma unroll
    for (int i = 0; i < 2; i++)
        #pragma unroll
        for (int j = 0; j < 8; j++)
            #pragma unroll
            for (int e = 0; e < 4; e++) acc[i][j][e] = 0.f;

    const int m0 = wm*32, n0 = wn*64;
    const int lr = lane & 15, lh = lane >> 4;

    ISSUE(0, 0); CP_COMMIT();
    ISSUE(1, 1); CP_COMMIT();

    int buf = 0;
    for (int s = 0; s < 32; s++) {
        if (s + 2 < 32) { ISSUE(s + 2, (s + 2) % 3); CP_COMMIT(); CP_WAIT2(); }
        else if (s + 1 < 32) { CP_WAIT1(); }
        else { CP_WAIT0(); }
        __syncthreads();

        const uint32_t As = smem_base + buf*STAGEB;
        const uint32_t Bs = As + TILEB;
        #pragma unroll
        for (int k = 0; k < 2; k++) {
            const uint32_t koff = k*32 + lh*16;
            uint32_t av[2][4], bq[4][4];
            #pragma unroll
            for (int mi = 0; mi < 2; mi++)
                LDSM4(av[mi], As + (m0 + mi*16 + lr)*ROWB + koff);
            #pragma unroll
            for (int jg = 0; jg < 4; jg++)
                LDSM4(bq[jg], Bs + (n0 + jg*16 + lr)*ROWB + koff);
            #pragma unroll
            for (int mi = 0; mi < 2; mi++)
                #pragma unroll
                for (int j = 0; j < 8; j++)
                    mma_f16(acc[mi][j], av[mi], bq[j>>1][j&1], bq[j>>1][(j&1)+2]);
        }
        __syncthreads();
        buf = (buf + 1 == 3) ? 0 : buf + 1;
    }
#undef ISSUE

    // epilogue
    const int g = lane >> 2, t = lane & 3;
    int colbase = bc*128;
    int mm = 0;
    if (MODE == 0) { mm = bc >> 3; colbase = (bc & 7)*128; }
    #pragma unroll
    for (int mi = 0; mi < 2; mi++) {
        #pragma unroll
        for (int rr = 0; rr < 2; rr++) {
            const int row = br*128 + m0 + mi*16 + rr*8 + g;
            #pragma unroll
            for (int j = 0; j < 8; j++) {
                const int col = colbase + n0 + j*8 + t*2;
                float vx = acc[mi][j][rr*2 + 0];
                float vy = acc[mi][j][rr*2 + 1];
                if (MODE == 1) {
                    float2 v; v.x = vx + bias[col]; v.y = vy + bias[col + 1];
                    *(float2*)&OUT[(size_t)row*DMODEL + col] = v;
                } else {
                    int bi = row >> 11, tt = row & 2047;
                    int h = col >> 6, dd = col & 63;
                    size_t o = (((size_t)(bi*NHEADS + h))*TSEQ + tt)*HDIM + dd;
                    __half* P = (mm == 0) ? QH : (mm == 1) ? KH : VH;
                    float sc = (mm == 0) ? SCALE_Q : 1.f;
                    *(uint32_t*)&P[o] = pack_h2(vx*sc, vy*sc);
                }
            }
        }
    }
}

// ---------------- HMMA flash attention -----------------------------------------
// S = Qh K^T (exp2 domain, fp16); O = Phi V; fp32 online softmax.
#define ROWF   144
#define FQH    0
#define FQTOT  (128*ROWF)        /* 18432 */
#define FKH    0
#define FVH    (64*ROWF)
#define FSTG   (2*64*ROWF)       /* 18432 */
#define FSMEM  (FQTOT + 2*FSTG)  /* 55296 */

__global__ __launch_bounds__(256, 2) void flash_hmma(
    const __half* __restrict__ qh,
    const __half* __restrict__ kh,  const __half* __restrict__ vh,
    __half* __restrict__ oh)
{
    extern __shared__ char fsm[];
    const uint32_t sb = smem_u32(fsm);
    const int tid = threadIdx.x, lane = tid & 31, wid = tid >> 5;
    const int bh = blockIdx.y, q0 = blockIdx.x*128;
    const int g = lane >> 2, t = lane & 3, lr = lane & 15, lh = lane >> 4;
    const int wq = wid*16;

    const size_t base = (size_t)bh*TSEQ*HDIM;
    const __half* qp = qh + base + (size_t)q0*HDIM;
    const __half* kp = kh + base;
    const __half* vp = vh + base;

    {
        int r = tid >> 1, c4 = (tid & 1)*4;
        #pragma unroll
        for (int u = 0; u < 4; u++)
            CP16(sb + FQH + r*ROWF + (c4+u)*16, qp + (size_t)r*HDIM + (c4+u)*8);
        CP_COMMIT();
    }

#define FISSUE(kb_, b_) do { \
    int r = tid >> 2, c2 = (tid & 3)*2; \
    uint32_t s0 = sb + FQTOT + (b_)*FSTG; \
    size_t go = (size_t)((kb_)*64 + r)*HDIM; \
    _Pragma("unroll") \
    for (int u = 0; u < 2; u++) { \
        CP16(s0 + FKH + r*ROWF + (c2+u)*16, kp + go + (c2+u)*8); \
        CP16(s0 + FVH + r*ROWF + (c2+u)*16, vp + go + (c2+u)*8); \
    } \
} while (0)

    FISSUE(0, 0); CP_COMMIT();
    CP_WAIT0(); __syncthreads();

    float oacc[8][4];
    #pragma unroll
    for (int j = 0; j < 8; j++)
        #pragma unroll
        for (int e = 0; e < 4; e++) oacc[j][e] = 0.f;
    const float NEGINF = __int_as_float(0xff800000);
    float m0 = NEGINF, m1 = NEGINF, l0 = 0.f, l1 = 0.f;

    for (int kb = 0; kb < 32; kb++) {
        if (kb + 1 < 32) { FISSUE(kb + 1, (kb + 1) & 1); CP_COMMIT(); CP_WAIT1(); }
        else             { CP_WAIT0(); }
        __syncthreads();

        const uint32_t SB = sb + FQTOT + (kb & 1)*FSTG;

        // ---- S = Q K^T (1-term), exp2 domain ----
        float sacc[8][4];
        #pragma unroll
        for (int j = 0; j < 8; j++)
            #pragma unroll
            for (int e = 0; e < 4; e++) sacc[j][e] = 0.f;

        #pragma unroll
        for (int kk = 0; kk < 4; kk++) {
            const uint32_t ko = kk*32 + lh*16;
            uint32_t aq[4];
            LDSM4(aq, sb + FQH + (wq + lr)*ROWF + ko);
            #pragma unroll
            for (int jg = 0; jg < 4; jg++) {
                uint32_t bkh[4];
                LDSM4(bkh, SB + FKH + (jg*16 + lr)*ROWF + ko);
                #pragma unroll
                for (int j2 = 0; j2 < 2; j2++)
                    mma_f16(sacc[jg*2 + j2], aq, bkh[j2], bkh[j2+2]);
            }
        }

        // ---- online softmax (exp2 domain) ----
        float nm0 = NEGINF, nm1 = NEGINF;
        #pragma unroll
        for (int j = 0; j < 8; j++) {
            nm0 = fmaxf(nm0, fmaxf(sacc[j][0], sacc[j][1]));
            nm1 = fmaxf(nm1, fmaxf(sacc[j][2], sacc[j][3]));
        }
        nm0 = fmaxf(nm0, __shfl_xor_sync(0xffffffffu, nm0, 1));
        nm0 = fmaxf(nm0, __shfl_xor_sync(0xffffffffu, nm0, 2));
        nm1 = fmaxf(nm1, __shfl_xor_sync(0xffffffffu, nm1, 1));
        nm1 = fmaxf(nm1, __shfl_xor_sync(0xffffffffu, nm1, 2));
        float M0 = fmaxf(m0, nm0), M1 = fmaxf(m1, nm1);
        bool changed = (M0 != m0) || (M1 != m1);
        float c0 = ex2f(m0 - M0), c1 = ex2f(m1 - M1);
        m0 = M0; m1 = M1;
        float rs0 = 0.f, rs1 = 0.f;
        #pragma unroll
        for (int j = 0; j < 8; j++) {
            sacc[j][0] = ex2f(sacc[j][0] - M0);
            sacc[j][1] = ex2f(sacc[j][1] - M0);
            sacc[j][2] = ex2f(sacc[j][2] - M1);
            sacc[j][3] = ex2f(sacc[j][3] - M1);
            rs0 += sacc[j][0] + sacc[j][1];
            rs1 += sacc[j][2] + sacc[j][3];
        }
        rs0 += __shfl_xor_sync(0xffffffffu, rs0, 1);
        rs0 += __shfl_xor_sync(0xffffffffu, rs0, 2);
        rs1 += __shfl_xor_sync(0xffffffffu, rs1, 1);
        rs1 += __shfl_xor_sync(0xffffffffu, rs1, 2);
        l0 = l0*c0 + rs0;
        l1 = l1*c1 + rs1;
        if (__any_sync(0xffffffffu, changed)) {
            #pragma unroll
            for (int j = 0; j < 8; j++) {
                oacc[j][0] *= c0; oacc[j][1] *= c0;
                oacc[j][2] *= c1; oacc[j][3] *= c1;
            }
        }

        // ---- O += Phi V (1-term); P repacked hi-only from S fragments ----
        const int vrow0 = ((lane >> 3) & 1)*8 + (lane & 7);
        const int vcsub = (lane >> 4)*8;
        #pragma unroll
        for (int kk = 0; kk < 4; kk++) {
            uint32_t ah[4];
            ah[0] = pack_h2(sacc[2*kk][0],   sacc[2*kk][1]);
            ah[1] = pack_h2(sacc[2*kk][2],   sacc[2*kk][3]);
            ah[2] = pack_h2(sacc[2*kk+1][0], sacc[2*kk+1][1]);
            ah[3] = pack_h2(sacc[2*kk+1][2], sacc[2*kk+1][3]);
            const uint32_t vr = (kk*16 + vrow0)*ROWF;
            #pragma unroll
            for (int jj = 0; jj < 4; jj++) {
                uint32_t bvh[4];
                LDSM4T(bvh, SB + FVH + vr + (jj*16 + vcsub)*2);
                #pragma unroll
                for (int j2 = 0; j2 < 2; j2++)
                    mma_f16(oacc[jj*2 + j2], ah, bvh[2*j2], bvh[2*j2+1]);
            }
        }
        __syncthreads();
    }
#undef FISSUE

    const float inv0 = 1.f / l0, inv1 = 1.f / l1;
    const int b = bh >> 4, h = bh & 15;
    const int tok0 = b*TSEQ + q0 + wq + g;
    const int tok1 = tok0 + 8;
    #pragma unroll
    for (int j = 0; j < 8; j++) {
        const int col = h*64 + j*8 + t*2;
        *(uint32_t*)&oh[(size_t)tok0*DMODEL + col] = pack_h2(oacc[j][0]*inv0, oacc[j][1]*inv0);
        *(uint32_t*)&oh[(size_t)tok1*DMODEL + col] = pack_h2(oacc[j][2]*inv1, oacc[j][3]*inv1);
    }
}

// ---------------- launch ----------------
extern "C" void kernel_launch(void* const* d_in, const int* in_sizes, int n_in,
                              void* d_out, int out_size)
{
    const float* x  = (const float*)d_in[0];
    const float* Wq = (const float*)d_in[1];
    const float* Wk = (const float*)d_in[2];
    const float* Wv = (const float*)d_in[3];
    const float* Wo = (const float*)d_in[4];
    const float* bo = (const float*)d_in[5];
    float* out = (float*)d_out;

    __half *xh, *wh, *ah, *qh, *kh, *vh;
    cudaGetSymbolAddress((void**)&xh, g_xh);
    cudaGetSymbolAddress((void**)&wh, g_wh);
    cudaGetSymbolAddress((void**)&ah, g_ah);
    cudaGetSymbolAddress((void**)&qh, g_qh);
    cudaGetSymbolAddress((void**)&kh, g_kh);
    cudaGetSymbolAddress((void**)&vh, g_vh);

    const size_t WSZ = (size_t)DMODEL*DMODEL;

    invf_kernel<<<1, 32>>>();
    rope_kernel<<<TSEQ, HDIM>>>();
    cvt_kernel<<<(BT*DMODEL/4 + 255)/256, 256>>>(x, xh, BT*DMODEL/4);
    gram1_kernel<<<64, 256>>>();
    gram2_kernel<<<HDIM, HDIM>>>();
    tsplit3_kernel<<<dim3(32, 32, 3), dim3(32, 8)>>>(Wq, Wk, Wo, wh);
    wvfold_kernel<<<dim3(32, 32), 256>>>(Wv, wh + 2*WSZ);

    cudaFuncSetAttribute(hgemm_tc<0>, cudaFuncAttributeMaxDynamicSharedMemorySize, SMEMB);
    cudaFuncSetAttribute(hgemm_tc<1>, cudaFuncAttributeMaxDynamicSharedMemorySize, SMEMB);
    cudaFuncSetAttribute(flash_hmma, cudaFuncAttributeMaxDynamicSharedMemorySize, FSMEM);

    // merged QKV projection: grid.x = 24 (3 matrices x 8 col-tiles)
    hgemm_tc<0><<<dim3(24, BT/128), 256, SMEMB>>>(xh, wh, nullptr, nullptr, qh, kh, vh);

    flash_hmma<<<dim3(TSEQ/128, BATCH*NHEADS), 256, FSMEM>>>(qh, kh, vh, ah);

    hgemm_tc<1><<<dim3(8, BT/128), 256, SMEMB>>>(ah, wh + 3*WSZ, bo, out,
                                                 nullptr, nullptr, nullptr);

    (void)in_sizes; (void)n_in; (void)out_size;
}

// round 16
// speedup vs baseline: 1.3813x; 1.0090x over previous
#include <cuda_runtime.h>
#include <cuda_fp16.h>
#include <math.h>
#include <stdint.h>

#define BATCH   2
#define TSEQ    2048
#define DMODEL  1024
#define NHEADS  16
#define HDIM    64
#define BT      (BATCH*TSEQ)   /* 4096 */
#define SCALE_Q 0.1803368801111137f   /* 0.125 * log2(e) */

// ---------------- scratch (static device arrays; no allocation) ----------------
__device__ float g_rope[TSEQ*HDIM];
__device__ double g_invf[32];
__device__ float g_MpartF[64][HDIM*HDIM];
__device__ float g_M[HDIM*HDIM];
__device__ __half g_xh[(size_t)BT*DMODEL];
__device__ __half g_wh[4*(size_t)DMODEL*DMODEL];   // transposed weights [N][K], fp16
__device__ __half g_qh[BATCH*NHEADS*TSEQ*HDIM];
__device__ __half g_kh[BATCH*NHEADS*TSEQ*HDIM];
__device__ __half g_vh[BATCH*NHEADS*TSEQ*HDIM];
__device__ __half g_ah[(size_t)BT*DMODEL];

// ---------------- PTX helpers (base ISA: cp.async / ldmatrix / mma.sync) --------
__device__ __forceinline__ uint32_t smem_u32(const void* p) {
    uint32_t a;
    asm("{ .reg .u64 t; cvta.to.shared.u64 t, %1; cvt.u32.u64 %0, t; }" : "=r"(a) : "l"(p));
    return a;
}
#define CP16(dst, src) asm volatile("cp.async.cg.shared.global [%0], [%1], 16;" :: "r"(dst), "l"(src))
#define CP_COMMIT()    asm volatile("cp.async.commit_group;" ::: "memory")
#define CP_WAIT3()     asm volatile("cp.async.wait_group 3;" ::: "memory")
#define CP_WAIT2()     asm volatile("cp.async.wait_group 2;" ::: "memory")
#define CP_WAIT1()     asm volatile("cp.async.wait_group 1;" ::: "memory")
#define CP_WAIT0()     asm volatile("cp.async.wait_group 0;" ::: "memory")
#define LDSM4(r, a) \
    asm volatile("ldmatrix.sync.aligned.m8n8.x4.shared.b16 {%0,%1,%2,%3}, [%4];" \
        : "=r"((r)[0]), "=r"((r)[1]), "=r"((r)[2]), "=r"((r)[3]) : "r"(a))
#define LDSM4T(r, a) \
    asm volatile("ldmatrix.sync.aligned.m8n8.x4.trans.shared.b16 {%0,%1,%2,%3}, [%4];" \
        : "=r"((r)[0]), "=r"((r)[1]), "=r"((r)[2]), "=r"((r)[3]) : "r"(a))
__device__ __forceinline__ void mma_f16(float* c, const uint32_t* a, uint32_t b0, uint32_t b1) {
    asm volatile("mma.sync.aligned.m16n8k16.row.col.f32.f16.f16.f32 "
                 "{%0,%1,%2,%3}, {%4,%5,%6,%7}, {%8,%9}, {%0,%1,%2,%3};"
                 : "+f"(c[0]), "+f"(c[1]), "+f"(c[2]), "+f"(c[3])
                 : "r"(a[0]), "r"(a[1]), "r"(a[2]), "r"(a[3]), "r"(b0), "r"(b1));
}
__device__ __forceinline__ float ex2f(float x) {
    float r; asm("ex2.approx.f32 %0, %1;" : "=f"(r) : "f"(x)); return r;
}
__device__ __forceinline__ uint32_t pack_h2(float x, float y) {
    __half2 h = __floats2half2_rn(x, y);
    return *(uint32_t*)&h;
}

// ---------------- rope / gram ----------------
__global__ void invf_kernel() {
    int j = threadIdx.x;
    g_invf[j] = exp(-log(10000.0) * (double)j / 32.0);
}
__global__ void rope_kernel() {
    int s = blockIdx.x, d = threadIdx.x;
    double ang = (double)s * g_invf[d & 31];
    g_rope[s*HDIM + d] = (d < 32) ? (float)cos(ang) : (float)sin(ang);
}
// Gram partials, fp32: 64 blocks x 256 threads; each block one 32-row chunk.
__global__ __launch_bounds__(256) void gram1_kernel() {
    __shared__ float R[32][68];
    const int c = blockIdx.x, tid = threadIdx.x;
    const float* rp = g_rope + (size_t)c*32*HDIM;
    for (int i = tid; i < 32*16; i += 256) {
        int r = i >> 4, q = i & 15;
        *(float4*)&R[r][q*4] = *(const float4*)(rp + r*HDIM + q*4);
    }
    __syncthreads();
    const int d0 = (tid & 15)*4, e0 = (tid >> 4)*4;
    float acc[4][4] = {};
    #pragma unroll 4
    for (int s = 0; s < 32; s++) {
        float4 a = *(const float4*)&R[s][d0];
        float4 b = *(const float4*)&R[s][e0];
        acc[0][0] = fmaf(a.x, b.x, acc[0][0]); acc[0][1] = fmaf(a.x, b.y, acc[0][1]);
        acc[0][2] = fmaf(a.x, b.z, acc[0][2]); acc[0][3] = fmaf(a.x, b.w, acc[0][3]);
        acc[1][0] = fmaf(a.y, b.x, acc[1][0]); acc[1][1] = fmaf(a.y, b.y, acc[1][1]);
        acc[1][2] = fmaf(a.y, b.z, acc[1][2]); acc[1][3] = fmaf(a.y, b.w, acc[1][3]);
        acc[2][0] = fmaf(a.z, b.x, acc[2][0]); acc[2][1] = fmaf(a.z, b.y, acc[2][1]);
        acc[2][2] = fmaf(a.z, b.z, acc[2][2]); acc[2][3] = fmaf(a.z, b.w, acc[2][3]);
        acc[3][0] = fmaf(a.w, b.x, acc[3][0]); acc[3][1] = fmaf(a.w, b.y, acc[3][1]);
        acc[3][2] = fmaf(a.w, b.z, acc[3][2]); acc[3][3] = fmaf(a.w, b.w, acc[3][3]);
    }
    #pragma unroll
    for (int i = 0; i < 4; i++)
        #pragma unroll
        for (int j = 0; j < 4; j++)
            g_MpartF[c][(d0 + i)*HDIM + e0 + j] = acc[i][j];
}
__global__ void gram2_kernel() {
    int d = blockIdx.x, e = threadIdx.x;
    float a = 0.f;
    #pragma unroll
    for (int c = 0; c < 64; c++) a += g_MpartF[c][d*HDIM + e];
    g_M[d*HDIM + e] = a;
}

// ---------------- fused fold+transpose+fp16: wh[2] = (Wv @ blockdiag(M))^T -------
__global__ __launch_bounds__(256) void wvfold_kernel(const float* __restrict__ Wv,
                                                     __half* __restrict__ whv) {
    __shared__ float Wt[32][65];   // [k_local][d]
    __shared__ float Mt[64][33];   // [d][e_local]
    const int n0 = blockIdx.x*32, k0 = blockIdx.y*32;
    const int h0 = n0 >> 6;
    const int e0 = n0 & 63;
    const int tid = threadIdx.x;
    for (int i = tid; i < 32*64; i += 256) {
        int r = i >> 6, c = i & 63;
        Wt[r][c] = Wv[(size_t)(k0 + r)*DMODEL + h0*64 + c];
    }
    for (int i = tid; i < 64*32; i += 256) {
        int d = i >> 5, e = i & 31;
        Mt[d][e] = g_M[d*HDIM + e0 + e];
    }
    __syncthreads();
    const int kl = tid & 31, nl0 = tid >> 5;
    #pragma unroll
    for (int u = 0; u < 4; u++) {
        int nl = nl0 + u*8;
        float acc = 0.f;
        #pragma unroll
        for (int d = 0; d < 64; d++) acc = fmaf(Wt[kl][d], Mt[d][nl], acc);
        whv[(size_t)(n0 + nl)*DMODEL + k0 + kl] = __float2half_rn(acc);
    }
}

// ---------------- fp16 convert of x ----------------
__global__ __launch_bounds__(256) void cvt_kernel(const float* __restrict__ src,
                                                  __half* __restrict__ dst, int n4) {
    int i = blockIdx.x*blockDim.x + threadIdx.x;
    if (i >= n4) return;
    float4 v = ((const float4*)src)[i];
    ((uint2*)dst)[i] = make_uint2(pack_h2(v.x, v.y), pack_h2(v.z, v.w));
}

// ---------------- batched transpose+round: {Wq,Wk,Wo} -> wh slots {0,1,3} --------
__global__ void tsplit3_kernel(const float* __restrict__ Wq,
                               const float* __restrict__ Wk,
                               const float* __restrict__ Wo,
                               __half* __restrict__ wh) {
    const int z = blockIdx.z;
    const float* W = (z == 0) ? Wq : (z == 1) ? Wk : Wo;
    __half* out = wh + (size_t)((z == 2) ? 3 : z)*DMODEL*DMODEL;
    __shared__ float t[32][33];
    int x0 = blockIdx.x*32, y0 = blockIdx.y*32;
    int tx = threadIdx.x, ty = threadIdx.y;
    #pragma unroll
    for (int j = 0; j < 32; j += 8)
        t[ty+j][tx] = W[(size_t)(y0+ty+j)*DMODEL + x0+tx];
    __syncthreads();
    #pragma unroll
    for (int j = 0; j < 32; j += 8)
        out[(size_t)(x0+ty+j)*DMODEL + y0+tx] = __float2half_rn(t[tx][ty+j]);
}

// ---------------- HMMA GEMM: C = Ah @ Bh^T, fp16, fp32 accum, 3-stage pipeline ---
#define ROWB     80
#define TILEB    (128*ROWB)
#define STAGEB   (2*TILEB)       /* 20480 */
#define SMEMB    (3*STAGEB)      /* 61440 */

template<int MODE>
__global__ __launch_bounds__(256) void hgemm_tc(const __half* __restrict__ Ah,
                                                const __half* __restrict__ Bh,
                                                const float* __restrict__ bias,
                                                float* __restrict__ OUT,
                                                __half* __restrict__ QH,
                                                __half* __restrict__ KH,
                                                __half* __restrict__ VH)
{
    extern __shared__ char smem[];
    const uint32_t smem_base = smem_u32(smem);
    const int tid  = threadIdx.x;
    const int lane = tid & 31;
    const int wid  = tid >> 5;
    const int wm   = wid & 3;
    const int wn   = wid >> 2;
    const int br   = blockIdx.y, bc = blockIdx.x;

    const int lrow  = tid >> 2;
    const int chunk = tid & 3;

    const __half* A0 = Ah + (size_t)(br*128 + lrow)*DMODEL + chunk*8;
    const __half* B0 = Bh + (size_t)(bc*128 + lrow)*DMODEL + chunk*8;
    const size_t rstep = (size_t)64*DMODEL;

#define ISSUE(s_, buf_) do { \
    uint32_t sb = smem_base + (buf_)*STAGEB; \
    uint32_t d0 = sb + lrow*ROWB + chunk*16; \
    size_t  go = (size_t)(s_)*32; \
    CP16(d0,         A0 + go); \
    CP16(d0 + TILEB, B0 + go); \
    uint32_t d1 = d0 + 64*ROWB; \
    CP16(d1,         A0 + go + rstep); \
    CP16(d1 + TILEB, B0 + go + rstep); \
} while (0)

    float acc[2][8][4];
    #pragma unroll
    for (int i = 0; i < 2; i++)
        #pragma unroll
        for (int j = 0; j < 8; j++)
            #pragma unroll
            for (int e = 0; e < 4; e++) acc[i][j][e] = 0.f;

    const int m0 = wm*32, n0 = wn*64;
    const int lr = lane & 15, lh = lane >> 4;

    ISSUE(0, 0); CP_COMMIT();
    ISSUE(1, 1); CP_COMMIT();

    int buf = 0;
    for (int s = 0; s < 32; s++) {
        if (s + 2 < 32) { ISSUE(s + 2, (s + 2) % 3); CP_COMMIT(); CP_WAIT2(); }
        else if (s + 1 < 32) { CP_WAIT1(); }
        else { CP_WAIT0(); }
        __syncthreads();

        const uint32_t As = smem_base + buf*STAGEB;
        const uint32_t Bs = As + TILEB;
        #pragma unroll
        for (int k = 0; k < 2; k++) {
            const uint32_t koff = k*32 + lh*16;
            uint32_t av[2][4], bq[4][4];
            #pragma unroll
            for (int mi = 0; mi < 2; mi++)
                LDSM4(av[mi], As + (m0 + mi*16 + lr)*ROWB + koff);
            #pragma unroll
            for (int jg = 0; jg < 4; jg++)
                LDSM4(bq[jg], Bs + (n0 + jg*16 + lr)*ROWB + koff);
            #pragma unroll
            for (int mi = 0; mi < 2; mi++)
                #pragma unroll
                for (int j = 0; j < 8; j++)
                    mma_f16(acc[mi][j], av[mi], bq[j>>1][j&1], bq[j>>1][(j&1)+2]);
        }
        __syncthreads();
        buf = (buf + 1 == 3) ? 0 : buf + 1;
    }
#undef ISSUE

    // epilogue
    const int g = lane >> 2, t = lane & 3;
    int colbase = bc*128;
    int mm = 0;
    if (MODE == 0) { mm = bc >> 3; colbase = (bc & 7)*128; }
    #pragma unroll
    for (int mi = 0; mi < 2; mi++) {
        #pragma unroll
        for (int rr = 0; rr < 2; rr++) {
            const int row = br*128 + m0 + mi*16 + rr*8 + g;
            #pragma unroll
            for (int j = 0; j < 8; j++) {
                const int col = colbase + n0 + j*8 + t*2;
                float vx = acc[mi][j][rr*2 + 0];
                float vy = acc[mi][j][rr*2 + 1];
                if (MODE == 1) {
                    float2 v; v.x = vx + bias[col]; v.y = vy + bias[col + 1];
                    *(float2*)&OUT[(size_t)row*DMODEL + col] = v;
                } else {
                    int bi = row >> 11, tt = row & 2047;
                    int h = col >> 6, dd = col & 63;
                    size_t o = (((size_t)(bi*NHEADS + h))*TSEQ + tt)*HDIM + dd;
                    __half* P = (mm == 0) ? QH : (mm == 1) ? KH : VH;
                    float sc = (mm == 0) ? SCALE_Q : 1.f;
                    *(uint32_t*)&P[o] = pack_h2(vx*sc, vy*sc);
                }
            }
        }
    }
}

// ---------------- HMMA flash attention -----------------------------------------
// S = Qh K^T (exp2 domain, fp16, Q in registers); O = Phi V; fp32 online softmax.
// 4-stage K/V ring, single barrier per iteration (issue distance 3, drift <= 1).
#define ROWF   144
#define FQH    0
#define FQTOT  (128*ROWF)        /* 18432 */
#define FKH    0
#define FVH    (64*ROWF)
#define FSTG   (2*64*ROWF)       /* 18432 */
#define FSMEM  (FQTOT + 4*FSTG)  /* 92160 */

__global__ __launch_bounds__(256, 2) void flash_hmma(
    const __half* __restrict__ qh,
    const __half* __restrict__ kh,  const __half* __restrict__ vh,
    __half* __restrict__ oh)
{
    extern __shared__ char fsm[];
    const uint32_t sb = smem_u32(fsm);
    const int tid = threadIdx.x, lane = tid & 31, wid = tid >> 5;
    const int bh = blockIdx.y, q0 = blockIdx.x*128;
    const int g = lane >> 2, t = lane & 3, lr = lane & 15, lh = lane >> 4;
    const int wq = wid*16;

    const size_t base = (size_t)bh*TSEQ*HDIM;
    const __half* qp = qh + base + (size_t)q0*HDIM;
    const __half* kp = kh + base;
    const __half* vp = vh + base;

    // group 0: Q
    {
        int r = tid >> 1, c4 = (tid & 1)*4;
        #pragma unroll
        for (int u = 0; u < 4; u++)
            CP16(sb + FQH + r*ROWF + (c4+u)*16, qp + (size_t)r*HDIM + (c4+u)*8);
        CP_COMMIT();
    }

#define FISSUE(kb_, b_) do { \
    int r = tid >> 2, c2 = (tid & 3)*2; \
    uint32_t s0 = sb + FQTOT + (b_)*FSTG; \
    size_t go = (size_t)((kb_)*64 + r)*HDIM; \
    _Pragma("unroll") \
    for (int u = 0; u < 2; u++) { \
        CP16(s0 + FKH + r*ROWF + (c2+u)*16, kp + go + (c2+u)*8); \
        CP16(s0 + FVH + r*ROWF + (c2+u)*16, vp + go + (c2+u)*8); \
    } \
} while (0)

    FISSUE(0, 0); CP_COMMIT();   // group 1
    FISSUE(1, 1); CP_COMMIT();   // group 2
    FISSUE(2, 2); CP_COMMIT();   // group 3

    // Q ready (wait_group 3 -> oldest group done), load Q fragments to registers
    CP_WAIT3();
    __syncthreads();
    uint32_t aq[4][4];
    #pragma unroll
    for (int kk = 0; kk < 4; kk++)
        LDSM4(aq[kk], sb + FQH + (wq + lr)*ROWF + kk*32 + lh*16);

    float oacc[8][4];
    #pragma unroll
    for (int j = 0; j < 8; j++)
        #pragma unroll
        for (int e = 0; e < 4; e++) oacc[j][e] = 0.f;
    const float NEGINF = __int_as_float(0xff800000);
    float m0 = NEGINF, m1 = NEGINF, l0 = 0.f, l1 = 0.f;

    for (int kb = 0; kb < 32; kb++) {
        // ensure stage kb complete (this thread), then barrier (all threads +
        // separates previous iteration's reads from this iteration's FISSUE)
        if (kb <= 29)      CP_WAIT2();
        else if (kb == 30) CP_WAIT1();
        else               CP_WAIT0();
        __syncthreads();
        if (kb + 3 < 32) { FISSUE(kb + 3, (kb + 3) & 3); CP_COMMIT(); }

        const uint32_t SB = sb + FQTOT + (kb & 3)*FSTG;

        // ---- S = Q K^T (Q in regs), exp2 domain ----
        float sacc[8][4];
        #pragma unroll
        for (int j = 0; j < 8; j++)
            #pragma unroll
            for (int e = 0; e < 4; e++) sacc[j][e] = 0.f;

        #pragma unroll
        for (int kk = 0; kk < 4; kk++) {
            const uint32_t ko = kk*32 + lh*16;
            #pragma unroll
            for (int jg = 0; jg < 4; jg++) {
                uint32_t bkh[4];
                LDSM4(bkh, SB + FKH + (jg*16 + lr)*ROWF + ko);
                #pragma unroll
                for (int j2 = 0; j2 < 2; j2++)
                    mma_f16(sacc[jg*2 + j2], aq[kk], bkh[j2], bkh[j2+2]);
            }
        }

        // ---- online softmax (exp2 domain) ----
        float nm0 = NEGINF, nm1 = NEGINF;
        #pragma unroll
        for (int j = 0; j < 8; j++) {
            nm0 = fmaxf(nm0, fmaxf(sacc[j][0], sacc[j][1]));
            nm1 = fmaxf(nm1, fmaxf(sacc[j][2], sacc[j][3]));
        }
        nm0 = fmaxf(nm0, __shfl_xor_sync(0xffffffffu, nm0, 1));
        nm0 = fmaxf(nm0, __shfl_xor_sync(0xffffffffu, nm0, 2));
        nm1 = fmaxf(nm1, __shfl_xor_sync(0xffffffffu, nm1, 1));
        nm1 = fmaxf(nm1, __shfl_xor_sync(0xffffffffu, nm1, 2));
        float M0 = fmaxf(m0, nm0), M1 = fmaxf(m1, nm1);
        bool changed = (M0 != m0) || (M1 != m1);
        float c0 = ex2f(m0 - M0), c1 = ex2f(m1 - M1);
        m0 = M0; m1 = M1;
        float rs0 = 0.f, rs1 = 0.f;
        #pragma unroll
        for (int j = 0; j < 8; j++) {
            sacc[j][0] = ex2f(sacc[j][0] - M0);
            sacc[j][1] = ex2f(sacc[j][1] - M0);
            sacc[j][2] = ex2f(sacc[j][2] - M1);
            sacc[j][3] = ex2f(sacc[j][3] - M1);
            rs0 += sacc[j][0] + sacc[j][1];
            rs1 += sacc[j][2] + sacc[j][3];
        }
        rs0 += __shfl_xor_sync(0xffffffffu, rs0, 1);
        rs0 += __shfl_xor_sync(0xffffffffu, rs0, 2);
        rs1 += __shfl_xor_sync(0xffffffffu, rs1, 1);
        rs1 += __shfl_xor_sync(0xffffffffu, rs1, 2);
        l0 = l0*c0 + rs0;
        l1 = l1*c1 + rs1;
        if (__any_sync(0xffffffffu, changed)) {
            #pragma unroll
            for (int j = 0; j < 8; j++) {
                oacc[j][0] *= c0; oacc[j][1] *= c0;
                oacc[j][2] *= c1; oacc[j][3] *= c1;
            }
        }

        // ---- O += Phi V; P repacked hi-only from S fragments ----
        const int vrow0 = ((lane >> 3) & 1)*8 + (lane & 7);
        const int vcsub = (lane >> 4)*8;
        #pragma unroll
        for (int kk = 0; kk < 4; kk++) {
            uint32_t ah[4];
            ah[0] = pack_h2(sacc[2*kk][0],   sacc[2*kk][1]);
            ah[1] = pack_h2(sacc[2*kk][2],   sacc[2*kk][3]);
            ah[2] = pack_h2(sacc[2*kk+1][0], sacc[2*kk+1][1]);
            ah[3] = pack_h2(sacc[2*kk+1][2], sacc[2*kk+1][3]);
            const uint32_t vr = (kk*16 + vrow0)*ROWF;
            #pragma unroll
            for (int jj = 0; jj < 4; jj++) {
                uint32_t bvh[4];
                LDSM4T(bvh, SB + FVH + vr + (jj*16 + vcsub)*2);
                #pragma unroll
                for (int j2 = 0; j2 < 2; j2++)
                    mma_f16(oacc[jj*2 + j2], ah, bvh[2*j2], bvh[2*j2+1]);
            }
        }
    }
#undef FISSUE

    const float inv0 = 1.f / l0, inv1 = 1.f / l1;
    const int b = bh >> 4, h = bh & 15;
    const int tok0 = b*TSEQ + q0 + wq + g;
    const int tok1 = tok0 + 8;
    #pragma unroll
    for (int j = 0; j < 8; j++) {
        const int col = h*64 + j*8 + t*2;
        *(uint32_t*)&oh[(size_t)tok0*DMODEL + col] = pack_h2(oacc[j][0]*inv0, oacc[j][1]*inv0);
        *(uint32_t*)&oh[(size_t)tok1*DMODEL + col] = pack_h2(oacc[j][2]*inv1, oacc[j][3]*inv1);
    }
}

// ---------------- launch ----------------
extern "C" void kernel_launch(void* const* d_in, const int* in_sizes, int n_in,
                              void* d_out, int out_size)
{
    const float* x  = (const float*)d_in[0];
    const float* Wq = (const float*)d_in[1];
    const float* Wk = (const float*)d_in[2];
    const float* Wv = (const float*)d_in[3];
    const float* Wo = (const float*)d_in[4];
    const float* bo = (const float*)d_in[5];
    float* out = (float*)d_out;

    __half *xh, *wh, *ah, *qh, *kh, *vh;
    cudaGetSymbolAddress((void**)&xh, g_xh);
    cudaGetSymbolAddress((void**)&wh, g_wh);
    cudaGetSymbolAddress((void**)&ah, g_ah);
    cudaGetSymbolAddress((void**)&qh, g_qh);
    cudaGetSymbolAddress((void**)&kh, g_kh);
    cudaGetSymbolAddress((void**)&vh, g_vh);

    const size_t WSZ = (size_t)DMODEL*DMODEL;

    invf_kernel<<<1, 32>>>();
    rope_kernel<<<TSEQ, HDIM>>>();
    cvt_kernel<<<(BT*DMODEL/4 + 255)/256, 256>>>(x, xh, BT*DMODEL/4);
    gram1_kernel<<<64, 256>>>();
    gram2_kernel<<<HDIM, HDIM>>>();
    tsplit3_kernel<<<dim3(32, 32, 3), dim3(32, 8)>>>(Wq, Wk, Wo, wh);
    wvfold_kernel<<<dim3(32, 32), 256>>>(Wv, wh + 2*WSZ);

    cudaFuncSetAttribute(hgemm_tc<0>, cudaFuncAttributeMaxDynamicSharedMemorySize, SMEMB);
    cudaFuncSetAttribute(hgemm_tc<1>, cudaFuncAttributeMaxDynamicSharedMemorySize, SMEMB);
    cudaFuncSetAttribute(flash_hmma, cudaFuncAttributeMaxDynamicSharedMemorySize, FSMEM);

    // merged QKV projection: grid.x = 24 (3 matrices x 8 col-tiles)
    hgemm_tc<0><<<dim3(24, BT/128), 256, SMEMB>>>(xh, wh, nullptr, nullptr, qh, kh, vh);

    flash_hmma<<<dim3(TSEQ/128, BATCH*NHEADS), 256, FSMEM>>>(qh, kh, vh, ah);

    hgemm_tc<1><<<dim3(8, BT/128), 256, SMEMB>>>(ah, wh + 3*WSZ, bo, out,
                                                 nullptr, nullptr, nullptr);

    (void)in_sizes; (void)n_in; (void)out_size;
}

// round 17
// speedup vs baseline: 1.5196x; 1.1001x over previous
#include <cuda_runtime.h>
#include <cuda_fp16.h>
#include <math.h>
#include <stdint.h>

#define BATCH   2
#define TSEQ    2048
#define DMODEL  1024
#define NHEADS  16
#define HDIM    64
#define BT      (BATCH*TSEQ)   /* 4096 */
#define SCALE_Q 0.1803368801111137f   /* 0.125 * log2(e) */

// ---------------- scratch (static device arrays; no allocation) ----------------
__device__ float g_rope[TSEQ*HDIM];
__device__ float g_MpartF[64][HDIM*HDIM];
__device__ float g_M[HDIM*HDIM];
__device__ __half g_xh[(size_t)BT*DMODEL];
__device__ __half g_wh[4*(size_t)DMODEL*DMODEL];   // transposed weights [N][K], fp16
__device__ __half g_qh[BATCH*NHEADS*TSEQ*HDIM];
__device__ __half g_kh[BATCH*NHEADS*TSEQ*HDIM];
__device__ __half g_vh[BATCH*NHEADS*TSEQ*HDIM];
__device__ __half g_ah[(size_t)BT*DMODEL];

// ---------------- PTX helpers (base ISA: cp.async / ldmatrix / mma.sync) --------
__device__ __forceinline__ uint32_t smem_u32(const void* p) {
    uint32_t a;
    asm("{ .reg .u64 t; cvta.to.shared.u64 t, %1; cvt.u32.u64 %0, t; }" : "=r"(a) : "l"(p));
    return a;
}
#define CP16(dst, src) asm volatile("cp.async.cg.shared.global [%0], [%1], 16;" :: "r"(dst), "l"(src))
#define CP_COMMIT()    asm volatile("cp.async.commit_group;" ::: "memory")
#define CP_WAIT3()     asm volatile("cp.async.wait_group 3;" ::: "memory")
#define CP_WAIT2()     asm volatile("cp.async.wait_group 2;" ::: "memory")
#define CP_WAIT1()     asm volatile("cp.async.wait_group 1;" ::: "memory")
#define CP_WAIT0()     asm volatile("cp.async.wait_group 0;" ::: "memory")
#define LDSM4(r, a) \
    asm volatile("ldmatrix.sync.aligned.m8n8.x4.shared.b16 {%0,%1,%2,%3}, [%4];" \
        : "=r"((r)[0]), "=r"((r)[1]), "=r"((r)[2]), "=r"((r)[3]) : "r"(a))
#define LDSM4T(r, a) \
    asm volatile("ldmatrix.sync.aligned.m8n8.x4.trans.shared.b16 {%0,%1,%2,%3}, [%4];" \
        : "=r"((r)[0]), "=r"((r)[1]), "=r"((r)[2]), "=r"((r)[3]) : "r"(a))
__device__ __forceinline__ void mma_f16(float* c, const uint32_t* a, uint32_t b0, uint32_t b1) {
    asm volatile("mma.sync.aligned.m16n8k16.row.col.f32.f16.f16.f32 "
                 "{%0,%1,%2,%3}, {%4,%5,%6,%7}, {%8,%9}, {%0,%1,%2,%3};"
                 : "+f"(c[0]), "+f"(c[1]), "+f"(c[2]), "+f"(c[3])
                 : "r"(a[0]), "r"(a[1]), "r"(a[2]), "r"(a[3]), "r"(b0), "r"(b1));
}
__device__ __forceinline__ float ex2f(float x) {
    float r; asm("ex2.approx.f32 %0, %1;" : "=f"(r) : "f"(x)); return r;
}
__device__ __forceinline__ uint32_t pack_h2(float x, float y) {
    __half2 h = __floats2half2_rn(x, y);
    return *(uint32_t*)&h;
}

// ---------------- prep1: rope (blocks 0..63) + x->fp16 convert (blocks 64..2047) -
__global__ __launch_bounds__(256) void prep1_kernel(const float* __restrict__ x,
                                                    __half* __restrict__ xh) {
    const int b = blockIdx.x;
    if (b < 64) {
        const int d  = threadIdx.x & 63;
        const int sl = threadIdx.x >> 6;      // 0..3
        const int j  = d & 31;
        const double invf = exp(-log(10000.0) * (double)j / 32.0);
        #pragma unroll
        for (int p = 0; p < 8; p++) {
            int s = b*32 + p*4 + sl;
            double ang = (double)s * invf;
            g_rope[s*HDIM + d] = (d < 32) ? (float)cos(ang) : (float)sin(ang);
        }
    } else {
        const int n4 = BT*DMODEL/4;
        const int stride = (2048 - 64)*256;
        for (int i = (b - 64)*256 + threadIdx.x; i < n4; i += stride) {
            float4 v = ((const float4*)x)[i];
            ((uint2*)xh)[i] = make_uint2(pack_h2(v.x, v.y), pack_h2(v.z, v.w));
        }
    }
}

// Gram partials, fp32: 64 blocks x 256 threads; each block one 32-row chunk.
__global__ __launch_bounds__(256) void gram1_kernel() {
    __shared__ float R[32][68];
    const int c = blockIdx.x, tid = threadIdx.x;
    const float* rp = g_rope + (size_t)c*32*HDIM;
    for (int i = tid; i < 32*16; i += 256) {
        int r = i >> 4, q = i & 15;
        *(float4*)&R[r][q*4] = *(const float4*)(rp + r*HDIM + q*4);
    }
    __syncthreads();
    const int d0 = (tid & 15)*4, e0 = (tid >> 4)*4;
    float acc[4][4] = {};
    #pragma unroll 4
    for (int s = 0; s < 32; s++) {
        float4 a = *(const float4*)&R[s][d0];
        float4 b = *(const float4*)&R[s][e0];
        acc[0][0] = fmaf(a.x, b.x, acc[0][0]); acc[0][1] = fmaf(a.x, b.y, acc[0][1]);
        acc[0][2] = fmaf(a.x, b.z, acc[0][2]); acc[0][3] = fmaf(a.x, b.w, acc[0][3]);
        acc[1][0] = fmaf(a.y, b.x, acc[1][0]); acc[1][1] = fmaf(a.y, b.y, acc[1][1]);
        acc[1][2] = fmaf(a.y, b.z, acc[1][2]); acc[1][3] = fmaf(a.y, b.w, acc[1][3]);
        acc[2][0] = fmaf(a.z, b.x, acc[2][0]); acc[2][1] = fmaf(a.z, b.y, acc[2][1]);
        acc[2][2] = fmaf(a.z, b.z, acc[2][2]); acc[2][3] = fmaf(a.z, b.w, acc[2][3]);
        acc[3][0] = fmaf(a.w, b.x, acc[3][0]); acc[3][1] = fmaf(a.w, b.y, acc[3][1]);
        acc[3][2] = fmaf(a.w, b.z, acc[3][2]); acc[3][3] = fmaf(a.w, b.w, acc[3][3]);
    }
    #pragma unroll
    for (int i = 0; i < 4; i++)
        #pragma unroll
        for (int j = 0; j < 4; j++)
            g_MpartF[c][(d0 + i)*HDIM + e0 + j] = acc[i][j];
}

// ---------------- fused: z<3 -> transpose+round {Wq,Wk,Wo}; z==3 -> gram2 --------
__global__ void tsg_kernel(const float* __restrict__ Wq,
                           const float* __restrict__ Wk,
                           const float* __restrict__ Wo,
                           __half* __restrict__ wh) {
    const int z = blockIdx.z;
    const int tid = threadIdx.y*32 + threadIdx.x;
    if (z == 3) {
        if (blockIdx.y != 0 || blockIdx.x >= 16) return;
        int idx = blockIdx.x*256 + tid;        // 0..4095
        int d = idx >> 6, e = idx & 63;
        float a = 0.f;
        #pragma unroll
        for (int c = 0; c < 64; c++) a += g_MpartF[c][d*HDIM + e];
        g_M[d*HDIM + e] = a;
        return;
    }
    const float* W = (z == 0) ? Wq : (z == 1) ? Wk : Wo;
    __half* out = wh + (size_t)((z == 2) ? 3 : z)*DMODEL*DMODEL;
    __shared__ float t[32][33];
    int x0 = blockIdx.x*32, y0 = blockIdx.y*32;
    int tx = threadIdx.x, ty = threadIdx.y;
    #pragma unroll
    for (int j = 0; j < 32; j += 8)
        t[ty+j][tx] = W[(size_t)(y0+ty+j)*DMODEL + x0+tx];
    __syncthreads();
    #pragma unroll
    for (int j = 0; j < 32; j += 8)
        out[(size_t)(x0+ty+j)*DMODEL + y0+tx] = __float2half_rn(t[tx][ty+j]);
}

// ---------------- fused fold+transpose+fp16: wh[2] = (Wv @ blockdiag(M))^T -------
__global__ __launch_bounds__(256) void wvfold_kernel(const float* __restrict__ Wv,
                                                     __half* __restrict__ whv) {
    __shared__ float Wt[32][65];   // [k_local][d]
    __shared__ float Mt[64][33];   // [d][e_local]
    const int n0 = blockIdx.x*32, k0 = blockIdx.y*32;
    const int h0 = n0 >> 6;
    const int e0 = n0 & 63;
    const int tid = threadIdx.x;
    for (int i = tid; i < 32*64; i += 256) {
        int r = i >> 6, c = i & 63;
        Wt[r][c] = Wv[(size_t)(k0 + r)*DMODEL + h0*64 + c];
    }
    for (int i = tid; i < 64*32; i += 256) {
        int d = i >> 5, e = i & 31;
        Mt[d][e] = g_M[d*HDIM + e0 + e];
    }
    __syncthreads();
    const int kl = tid & 31, nl0 = tid >> 5;
    #pragma unroll
    for (int u = 0; u < 4; u++) {
        int nl = nl0 + u*8;
        float acc = 0.f;
        #pragma unroll
        for (int d = 0; d < 64; d++) acc = fmaf(Wt[kl][d], Mt[d][nl], acc);
        whv[(size_t)(n0 + nl)*DMODEL + k0 + kl] = __float2half_rn(acc);
    }
}

// ---- HMMA GEMM: C = Ah @ Bh^T, fp16, fp32 accum, 4-stage ring, 1 barrier/iter ---
#define ROWB     80
#define TILEB    (128*ROWB)
#define STAGEB   (2*TILEB)       /* 20480 */
#define SMEMB    (4*STAGEB)      /* 81920 */

template<int MODE>
__global__ __launch_bounds__(256) void hgemm_tc(const __half* __restrict__ Ah,
                                                const __half* __restrict__ Bh,
                                                const float* __restrict__ bias,
                                                float* __restrict__ OUT,
                                                __half* __restrict__ QH,
                                                __half* __restrict__ KH,
                                                __half* __restrict__ VH)
{
    extern __shared__ char smem[];
    const uint32_t smem_base = smem_u32(smem);
    const int tid  = threadIdx.x;
    const int lane = tid & 31;
    const int wid  = tid >> 5;
    const int wm   = wid & 3;
    const int wn   = wid >> 2;
    const int br   = blockIdx.y, bc = blockIdx.x;

    const int lrow  = tid >> 2;
    const int chunk = tid & 3;

    const __half* A0 = Ah + (size_t)(br*128 + lrow)*DMODEL + chunk*8;
    const __half* B0 = Bh + (size_t)(bc*128 + lrow)*DMODEL + chunk*8;
    const size_t rstep = (size_t)64*DMODEL;

#define ISSUE(s_, buf_) do { \
    uint32_t sb = smem_base + (buf_)*STAGEB; \
    uint32_t d0 = sb + lrow*ROWB + chunk*16; \
    size_t  go = (size_t)(s_)*32; \
    CP16(d0,         A0 + go); \
    CP16(d0 + TILEB, B0 + go); \
    uint32_t d1 = d0 + 64*ROWB; \
    CP16(d1,         A0 + go + rstep); \
    CP16(d1 + TILEB, B0 + go + rstep); \
} while (0)

    float acc[2][8][4];
    #pragma unroll
    for (int i = 0; i < 2; i++)
        #pragma unroll
        for (int j = 0; j < 8; j++)
            #pragma unroll
            for (int e = 0; e < 4; e++) acc[i][j][e] = 0.f;

    const int m0 = wm*32, n0 = wn*64;
    const int lr = lane & 15, lh = lane >> 4;

    ISSUE(0, 0); CP_COMMIT();
    ISSUE(1, 1); CP_COMMIT();
    ISSUE(2, 2); CP_COMMIT();

    for (int s = 0; s < 32; s++) {
        if (s <= 29)      CP_WAIT2();
        else if (s == 30) CP_WAIT1();
        else              CP_WAIT0();
        __syncthreads();
        if (s + 3 < 32) { ISSUE(s + 3, (s + 3) & 3); CP_COMMIT(); }

        const uint32_t As = smem_base + (s & 3)*STAGEB;
        const uint32_t Bs = As + TILEB;
        #pragma unroll
        for (int k = 0; k < 2; k++) {
            const uint32_t koff = k*32 + lh*16;
            uint32_t av[2][4], bq[4][4];
            #pragma unroll
            for (int mi = 0; mi < 2; mi++)
                LDSM4(av[mi], As + (m0 + mi*16 + lr)*ROWB + koff);
            #pragma unroll
            for (int jg = 0; jg < 4; jg++)
                LDSM4(bq[jg], Bs + (n0 + jg*16 + lr)*ROWB + koff);
            #pragma unroll
            for (int mi = 0; mi < 2; mi++)
                #pragma unroll
                for (int j = 0; j < 8; j++)
                    mma_f16(acc[mi][j], av[mi], bq[j>>1][j&1], bq[j>>1][(j&1)+2]);
        }
    }
#undef ISSUE

    // epilogue
    const int g = lane >> 2, t = lane & 3;
    int colbase = bc*128;
    int mm = 0;
    if (MODE == 0) { mm = bc >> 3; colbase = (bc & 7)*128; }
    #pragma unroll
    for (int mi = 0; mi < 2; mi++) {
        #pragma unroll
        for (int rr = 0; rr < 2; rr++) {
            const int row = br*128 + m0 + mi*16 + rr*8 + g;
            #pragma unroll
            for (int j = 0; j < 8; j++) {
                const int col = colbase + n0 + j*8 + t*2;
                float vx = acc[mi][j][rr*2 + 0];
                float vy = acc[mi][j][rr*2 + 1];
                if (MODE == 1) {
                    float2 v; v.x = vx + bias[col]; v.y = vy + bias[col + 1];
                    *(float2*)&OUT[(size_t)row*DMODEL + col] = v;
                } else {
                    int bi = row >> 11, tt = row & 2047;
                    int h = col >> 6, dd = col & 63;
                    size_t o = (((size_t)(bi*NHEADS + h))*TSEQ + tt)*HDIM + dd;
                    __half* P = (mm == 0) ? QH : (mm == 1) ? KH : VH;
                    float sc = (mm == 0) ? SCALE_Q : 1.f;
                    *(uint32_t*)&P[o] = pack_h2(vx*sc, vy*sc);
                }
            }
        }
    }
}

// ---------------- HMMA flash attention -----------------------------------------
// S = Qh K^T (exp2 domain, fp16, Q in registers); O = Phi V; fp32 online softmax.
// 4-stage K/V ring, single barrier per iteration.
#define ROWF   144
#define FQH    0
#define FQTOT  (128*ROWF)        /* 18432 */
#define FKH    0
#define FVH    (64*ROWF)
#define FSTG   (2*64*ROWF)       /* 18432 */
#define FSMEM  (FQTOT + 4*FSTG)  /* 92160 */

__global__ __launch_bounds__(256, 2) void flash_hmma(
    const __half* __restrict__ qh,
    const __half* __restrict__ kh,  const __half* __restrict__ vh,
    __half* __restrict__ oh)
{
    extern __shared__ char fsm[];
    const uint32_t sb = smem_u32(fsm);
    const int tid = threadIdx.x, lane = tid & 31, wid = tid >> 5;
    const int bh = blockIdx.y, q0 = blockIdx.x*128;
    const int g = lane >> 2, t = lane & 3, lr = lane & 15, lh = lane >> 4;
    const int wq = wid*16;

    const size_t base = (size_t)bh*TSEQ*HDIM;
    const __half* qp = qh + base + (size_t)q0*HDIM;
    const __half* kp = kh + base;
    const __half* vp = vh + base;

    // group 0: Q
    {
        int r = tid >> 1, c4 = (tid & 1)*4;
        #pragma unroll
        for (int u = 0; u < 4; u++)
            CP16(sb + FQH + r*ROWF + (c4+u)*16, qp + (size_t)r*HDIM + (c4+u)*8);
        CP_COMMIT();
    }

#define FISSUE(kb_, b_) do { \
    int r = tid >> 2, c2 = (tid & 3)*2; \
    uint32_t s0 = sb + FQTOT + (b_)*FSTG; \
    size_t go = (size_t)((kb_)*64 + r)*HDIM; \
    _Pragma("unroll") \
    for (int u = 0; u < 2; u++) { \
        CP16(s0 + FKH + r*ROWF + (c2+u)*16, kp + go + (c2+u)*8); \
        CP16(s0 + FVH + r*ROWF + (c2+u)*16, vp + go + (c2+u)*8); \
    } \
} while (0)

    FISSUE(0, 0); CP_COMMIT();   // group 1
    FISSUE(1, 1); CP_COMMIT();   // group 2
    FISSUE(2, 2); CP_COMMIT();   // group 3

    // Q ready, load Q fragments to registers
    CP_WAIT3();
    __syncthreads();
    uint32_t aq[4][4];
    #pragma unroll
    for (int kk = 0; kk < 4; kk++)
        LDSM4(aq[kk], sb + FQH + (wq + lr)*ROWF + kk*32 + lh*16);

    float oacc[8][4];
    #pragma unroll
    for (int j = 0; j < 8; j++)
        #pragma unroll
        for (int e = 0; e < 4; e++) oacc[j][e] = 0.f;
    const float NEGINF = __int_as_float(0xff800000);
    float m0 = NEGINF, m1 = NEGINF, l0 = 0.f, l1 = 0.f;

    for (int kb = 0; kb < 32; kb++) {
        if (kb <= 29)      CP_WAIT2();
        else if (kb == 30) CP_WAIT1();
        else               CP_WAIT0();
        __syncthreads();
        if (kb + 3 < 32) { FISSUE(kb + 3, (kb + 3) & 3); CP_COMMIT(); }

        const uint32_t SB = sb + FQTOT + (kb & 3)*FSTG;

        // ---- S = Q K^T (Q in regs), exp2 domain ----
        float sacc[8][4];
        #pragma unroll
        for (int j = 0; j < 8; j++)
            #pragma unroll
            for (int e = 0; e < 4; e++) sacc[j][e] = 0.f;

        #pragma unroll
        for (int kk = 0; kk < 4; kk++) {
            const uint32_t ko = kk*32 + lh*16;
            #pragma unroll
            for (int jg = 0; jg < 4; jg++) {
                uint32_t bkh[4];
                LDSM4(bkh, SB + FKH + (jg*16 + lr)*ROWF + ko);
                #pragma unroll
                for (int j2 = 0; j2 < 2; j2++)
                    mma_f16(sacc[jg*2 + j2], aq[kk], bkh[j2], bkh[j2+2]);
            }
        }

        // ---- online softmax (exp2 domain) ----
        float nm0 = NEGINF, nm1 = NEGINF;
        #pragma unroll
        for (int j = 0; j < 8; j++) {
            nm0 = fmaxf(nm0, fmaxf(sacc[j][0], sacc[j][1]));
            nm1 = fmaxf(nm1, fmaxf(sacc[j][2], sacc[j][3]));
        }
        nm0 = fmaxf(nm0, __shfl_xor_sync(0xffffffffu, nm0, 1));
        nm0 = fmaxf(nm0, __shfl_xor_sync(0xffffffffu, nm0, 2));
        nm1 = fmaxf(nm1, __shfl_xor_sync(0xffffffffu, nm1, 1));
        nm1 = fmaxf(nm1, __shfl_xor_sync(0xffffffffu, nm1, 2));
        float M0 = fmaxf(m0, nm0), M1 = fmaxf(m1, nm1);
        bool changed = (M0 != m0) || (M1 != m1);
        float c0 = ex2f(m0 - M0), c1 = ex2f(m1 - M1);
        m0 = M0; m1 = M1;
        float rs0 = 0.f, rs1 = 0.f;
        #pragma unroll
        for (int j = 0; j < 8; j++) {
            sacc[j][0] = ex2f(sacc[j][0] - M0);
            sacc[j][1] = ex2f(sacc[j][1] - M0);
            sacc[j][2] = ex2f(sacc[j][2] - M1);
            sacc[j][3] = ex2f(sacc[j][3] - M1);
            rs0 += sacc[j][0] + sacc[j][1];
            rs1 += sacc[j][2] + sacc[j][3];
        }
        rs0 += __shfl_xor_sync(0xffffffffu, rs0, 1);
        rs0 += __shfl_xor_sync(0xffffffffu, rs0, 2);
        rs1 += __shfl_xor_sync(0xffffffffu, rs1, 1);
        rs1 += __shfl_xor_sync(0xffffffffu, rs1, 2);
        l0 = l0*c0 + rs0;
        l1 = l1*c1 + rs1;
        if (__any_sync(0xffffffffu, changed)) {
            #pragma unroll
            for (int j = 0; j < 8; j++) {
                oacc[j][0] *= c0; oacc[j][1] *= c0;
                oacc[j][2] *= c1; oacc[j][3] *= c1;
            }
        }

        // ---- O += Phi V; P repacked hi-only from S fragments ----
        const int vrow0 = ((lane >> 3) & 1)*8 + (lane & 7);
        const int vcsub = (lane >> 4)*8;
        #pragma unroll
        for (int kk = 0; kk < 4; kk++) {
            uint32_t ah[4];
            ah[0] = pack_h2(sacc[2*kk][0],   sacc[2*kk][1]);
            ah[1] = pack_h2(sacc[2*kk][2],   sacc[2*kk][3]);
            ah[2] = pack_h2(sacc[2*kk+1][0], sacc[2*kk+1][1]);
            ah[3] = pack_h2(sacc[2*kk+1][2], sacc[2*kk+1][3]);
            const uint32_t vr = (kk*16 + vrow0)*ROWF;
            #pragma unroll
            for (int jj = 0; jj < 4; jj++) {
                uint32_t bvh[4];
                LDSM4T(bvh, SB + FVH + vr + (jj*16 + vcsub)*2);
                #pragma unroll
                for (int j2 = 0; j2 < 2; j2++)
                    mma_f16(oacc[jj*2 + j2], ah, bvh[2*j2], bvh[2*j2+1]);
            }
        }
    }
#undef FISSUE

    const float inv0 = 1.f / l0, inv1 = 1.f / l1;
    const int b = bh >> 4, h = bh & 15;
    const int tok0 = b*TSEQ + q0 + wq + g;
    const int tok1 = tok0 + 8;
    #pragma unroll
    for (int j = 0; j < 8; j++) {
        const int col = h*64 + j*8 + t*2;
        *(uint32_t*)&oh[(size_t)tok0*DMODEL + col] = pack_h2(oacc[j][0]*inv0, oacc[j][1]*inv0);
        *(uint32_t*)&oh[(size_t)tok1*DMODEL + col] = pack_h2(oacc[j][2]*inv1, oacc[j][3]*inv1);
    }
}

// ---------------- launch ----------------
extern "C" void kernel_launch(void* const* d_in, const int* in_sizes, int n_in,
                              void* d_out, int out_size)
{
    const float* x  = (const float*)d_in[0];
    const float* Wq = (const float*)d_in[1];
    const float* Wk = (const float*)d_in[2];
    const float* Wv = (const float*)d_in[3];
    const float* Wo = (const float*)d_in[4];
    const float* bo = (const float*)d_in[5];
    float* out = (float*)d_out;

    __half *xh, *wh, *ah, *qh, *kh, *vh;
    cudaGetSymbolAddress((void**)&xh, g_xh);
    cudaGetSymbolAddress((void**)&wh, g_wh);
    cudaGetSymbolAddress((void**)&ah, g_ah);
    cudaGetSymbolAddress((void**)&qh, g_qh);
    cudaGetSymbolAddress((void**)&kh, g_kh);
    cudaGetSymbolAddress((void**)&vh, g_vh);

    const size_t WSZ = (size_t)DMODEL*DMODEL;

    prep1_kernel<<<2048, 256>>>(x, xh);                       // rope + x->fp16
    gram1_kernel<<<64, 256>>>();
    tsg_kernel<<<dim3(32, 32, 4), dim3(32, 8)>>>(Wq, Wk, Wo, wh);  // tsplit x3 + gram2
    wvfold_kernel<<<dim3(32, 32), 256>>>(Wv, wh + 2*WSZ);

    cudaFuncSetAttribute(hgemm_tc<0>, cudaFuncAttributeMaxDynamicSharedMemorySize, SMEMB);
    cudaFuncSetAttribute(hgemm_tc<1>, cudaFuncAttributeMaxDynamicSharedMemorySize, SMEMB);
    cudaFuncSetAttribute(flash_hmma, cudaFuncAttributeMaxDynamicSharedMemorySize, FSMEM);

    // merged QKV projection: grid.x = 24 (3 matrices x 8 col-tiles)
    hgemm_tc<0><<<dim3(24, BT/128), 256, SMEMB>>>(xh, wh, nullptr, nullptr, qh, kh, vh);

    flash_hmma<<<dim3(TSEQ/128, BATCH*NHEADS), 256, FSMEM>>>(qh, kh, vh, ah);

    hgemm_tc<1><<<dim3(8, BT/128), 256, SMEMB>>>(ah, wh + 3*WSZ, bo, out,
                                                 nullptr, nullptr, nullptr);

    (void)in_sizes; (void)n_in; (void)out_size;
}